// round 5
// baseline (speedup 1.0000x reference)
#include <cuda_runtime.h>
#include <math.h>

#define HDIM 1024
#define LDIM 512
#define VDIM 50257
#define NB   592
#define NT   256
#define NWARPS (NB * 8)

// Wo prefetch plan (float4 units). Total Wo = 50257*256 = 12,865,792 float4.
// Prefetch first ~99.5 MB into L2 during phases 1-4 using idle blocks.
#define P1_START 192
#define P1_N4    12
#define P1_BASE  0L
#define P2_START 128
#define P2_N4    14
#define P2_BASE  1228800L            // 400*256*12
#define P3_BASE  2891776L            // P2_BASE + 464*256*14
#define P4_BASE  4554752L            // P3_BASE + 464*256*14

// ---------------- device scratch (no allocations allowed) ----------------
__device__ float g_attn[LDIM];
__device__ float g_wctx[HDIM];
__device__ float g_vout[HDIM];
__device__ float g_gh[3 * HDIM];
__device__ float g_hnew[HDIM];
__device__ float g_logits[VDIM];
__device__ float g_expsum;
__device__ float g_sink;
__device__ unsigned g_bar_cnt = 0;
__device__ volatile unsigned g_bar_gen = 0;

// ---------------- software grid barrier (all NB blocks co-resident) ------
__device__ __forceinline__ void grid_barrier() {
    __syncthreads();
    if (threadIdx.x == 0) {
        unsigned gen = g_bar_gen;
        __threadfence();
        unsigned t = atomicAdd(&g_bar_cnt, 1u);
        if (t == NB - 1) {
            g_bar_cnt = 0;
            __threadfence();
            g_bar_gen = gen + 1;
        } else {
            while (g_bar_gen == gen) __nanosleep(64);
        }
        __threadfence();
    }
    __syncthreads();
}

__device__ __forceinline__ float warpReduce(float v) {
    #pragma unroll
    for (int o = 16; o; o >>= 1) v += __shfl_down_sync(0xffffffffu, v, o);
    return v;
}

// L2 prefetch of Wo chunk: dead loads kept alive by sentinel-guarded sink.
template<int N4>
__device__ __forceinline__ void prefetch_wo(const uint4* wo4, long base) {
    unsigned acc = 0;
    #pragma unroll
    for (int k = 0; k < N4; k++) {
        uint4 v = __ldcg(wo4 + base + k);
        acc ^= v.x ^ v.w;
    }
    if (acc == 0xDEADBEEFu) g_sink = 1.f;   // never true in practice; keeps LDGs
}

__global__ void __launch_bounds__(NT, 4)
fused_decoder(const int* __restrict__ x, const float* __restrict__ hidden,
              const float* __restrict__ enc, const float* __restrict__ emb,
              const float* __restrict__ Ww, const float* __restrict__ bw,
              const float* __restrict__ Wc, const float* __restrict__ bc,
              const float* __restrict__ Wih, const float* __restrict__ Whh,
              const float* __restrict__ bih, const float* __restrict__ bhh,
              const float* __restrict__ Wo, const float* __restrict__ bo,
              float* __restrict__ out) {
    __shared__ float sbuf[2048];
    __shared__ float sred[256];
    __shared__ float swarp[8];
    __shared__ float s_m, s_inv;

    const int blk = blockIdx.x, t = threadIdx.x;
    const int warp = t >> 5, lane = t & 31;
    float4* sb4 = (float4*)sbuf;
    const uint4* wo4 = (const uint4*)Wo;

    // ================= Phase 1: attn + gh + prefetch P1 ====================
    if (blk < 64) {
        const float4* e4 = (const float4*)(emb + (size_t)x[0] * HDIM);
        const float4* h4 = (const float4*)hidden;
        sb4[t] = e4[t];
        sb4[256 + t] = h4[t];
        __syncthreads();
        int row = blk * 8 + warp;
        const float4* w4 = (const float4*)Ww + (size_t)row * 512;
        float acc = 0.f;
        #pragma unroll
        for (int k = 0; k < 16; k++) {
            int idx = k * 32 + lane;
            float4 a = __ldcs(w4 + idx), b = sb4[idx];
            acc += a.x * b.x + a.y * b.y + a.z * b.z + a.w * b.w;
        }
        acc = warpReduce(acc);
        if (lane == 0) g_attn[row] = acc + bw[row];
    } else if (blk < P1_START) {
        // gh rows (3072 rows over 1024 warps -> 3 rows each)
        if (blk == 64) {
            g_wctx[t] = 0.f; g_wctx[t + 256] = 0.f;
            g_wctx[t + 512] = 0.f; g_wctx[t + 768] = 0.f;
            if (t == 0) g_expsum = 0.f;
        }
        const float4* h4 = (const float4*)hidden;
        sb4[t] = h4[t];
        __syncthreads();
        int gw = (blk - 64) * 8 + warp;
        #pragma unroll
        for (int rep = 0; rep < 3; rep++) {
            int r = gw + rep * 1024;
            const float4* w4 = (const float4*)Whh + (size_t)r * 256;
            float acc = 0.f;
            #pragma unroll
            for (int k = 0; k < 8; k++) {
                int idx = k * 32 + lane;
                float4 a = __ldcs(w4 + idx), b = sb4[idx];
                acc += a.x * b.x + a.y * b.y + a.z * b.z + a.w * b.w;
            }
            acc = warpReduce(acc);
            if (lane == 0) g_gh[r] = acc + bhh[r];
        }
    } else {
        long tid_p = (long)(blk - P1_START) * NT + t;
        prefetch_wo<P1_N4>(wo4, P1_BASE + tid_p * P1_N4);
    }
    grid_barrier();

    // ================= Phase 2: softmax + wctx | prefetch P2 ==============
    if (blk < 128) {
        sbuf[t] = __ldcg(g_attn + t);
        sbuf[t + 256] = __ldcg(g_attn + t + 256);
        __syncthreads();
        sred[t] = fmaxf(sbuf[t], sbuf[t + 256]);
        __syncthreads();
        #pragma unroll
        for (int o = 128; o; o >>= 1) { if (t < o) sred[t] = fmaxf(sred[t], sred[t + o]); __syncthreads(); }
        if (t == 0) s_m = sred[0];
        __syncthreads();
        float m = s_m;
        sred[t] = expf(sbuf[t] - m) + expf(sbuf[t + 256] - m);
        __syncthreads();
        #pragma unroll
        for (int o = 128; o; o >>= 1) { if (t < o) sred[t] += sred[t + o]; __syncthreads(); }
        if (t == 0) s_inv = 1.f / sred[0];
        __syncthreads();
        float inv = s_inv;

        int c = blk & 3, lch = blk >> 2;       // 4 col-chunks x 32 L-chunks
        int l0 = lch * 16;
        int col = c * 256 + t;
        float acc = 0.f;
        #pragma unroll
        for (int j = 0; j < 16; j++) {
            float w = expf(sbuf[l0 + j] - m);
            acc += w * __ldcs(&enc[(size_t)(l0 + j) * HDIM + col]);
        }
        atomicAdd(&g_wctx[col], acc * inv);

        if (blk == 0) {   // weights output
            out[VDIM + HDIM + t] = expf(sbuf[t] - m) * inv;
            out[VDIM + HDIM + t + 256] = expf(sbuf[t + 256] - m) * inv;
        }
    } else {
        long tid_p = (long)(blk - P2_START) * NT + t;
        prefetch_wo<P2_N4>(wo4, P2_BASE + tid_p * P2_N4);
    }
    grid_barrier();

    // ================= Phase 3: vout | prefetch P3 =========================
    if (blk < 128) {
        const float4* e4 = (const float4*)(emb + (size_t)x[0] * HDIM);
        sb4[t] = e4[t];
        sb4[256 + t] = __ldcg((const float4*)g_wctx + t);
        __syncthreads();
        int row = blk * 8 + warp;
        const float4* w4 = (const float4*)Wc + (size_t)row * 512;
        float acc = 0.f;
        #pragma unroll
        for (int k = 0; k < 16; k++) {
            int idx = k * 32 + lane;
            float4 a = __ldcs(w4 + idx), b = sb4[idx];
            acc += a.x * b.x + a.y * b.y + a.z * b.z + a.w * b.w;
        }
        acc = warpReduce(acc);
        if (lane == 0) g_vout[row] = fmaxf(acc + bc[row], 0.f);
    } else {
        long tid_p = (long)(blk - P2_START) * NT + t;
        prefetch_wo<P2_N4>(wo4, P3_BASE + tid_p * P2_N4);
    }
    grid_barrier();

    // ================= Phase 4: GRU + h_new | prefetch P4 ==================
    if (blk < 128) {
        sb4[t] = __ldcg((const float4*)g_vout + t);
        __syncthreads();
        int i = blk * 8 + warp;   // 0..1023
        const float4* wr = (const float4*)Wih + (size_t)i * 256;
        const float4* wz = (const float4*)Wih + (size_t)(i + HDIM) * 256;
        const float4* wn = (const float4*)Wih + (size_t)(i + 2 * HDIM) * 256;
        float a0 = 0.f, a1 = 0.f, a2 = 0.f;
        #pragma unroll
        for (int k = 0; k < 8; k++) {
            int idx = k * 32 + lane;
            float4 b = sb4[idx];
            float4 m0 = __ldcs(wr + idx); a0 += m0.x * b.x + m0.y * b.y + m0.z * b.z + m0.w * b.w;
            float4 m1 = __ldcs(wz + idx); a1 += m1.x * b.x + m1.y * b.y + m1.z * b.z + m1.w * b.w;
            float4 m2 = __ldcs(wn + idx); a2 += m2.x * b.x + m2.y * b.y + m2.z * b.z + m2.w * b.w;
        }
        a0 = warpReduce(a0); a1 = warpReduce(a1); a2 = warpReduce(a2);
        if (lane == 0) {
            float gh_r = __ldcg(&g_gh[i]);
            float gh_z = __ldcg(&g_gh[i + HDIM]);
            float gh_n = __ldcg(&g_gh[i + 2 * HDIM]);
            float gi_r = a0 + bih[i];
            float gi_z = a1 + bih[i + HDIM];
            float gi_n = a2 + bih[i + 2 * HDIM];
            float r = 1.f / (1.f + expf(-(gi_r + gh_r)));
            float z = 1.f / (1.f + expf(-(gi_z + gh_z)));
            float n = tanhf(gi_n + r * gh_n);
            float hn = (1.f - z) * n + z * hidden[i];
            g_hnew[i] = hn;
            out[VDIM + i] = hn;
        }
    } else {
        long tid_p = (long)(blk - P2_START) * NT + t;
        prefetch_wo<P2_N4>(wo4, P4_BASE + tid_p * P2_N4);
    }
    grid_barrier();

    // ================= Phase 5: vocab GEMV + exp-sum (2 rows/warp iter) ====
    {
        sb4[t] = __ldcg((const float4*)g_hnew + t);
        __syncthreads();
        int gw = blk * 8 + warp;
        float esum = 0.f;
        for (int r = gw; r < VDIM; r += 2 * NWARPS) {
            int rB = r + NWARPS;
            bool vB = rB < VDIM;
            const float4* wA = (const float4*)Wo + (size_t)r * 256;
            const float4* wB = (const float4*)Wo + (size_t)rB * 256;
            float accA = 0.f, accB = 0.f;
            #pragma unroll
            for (int k = 0; k < 8; k++) {
                int idx = k * 32 + lane;
                float4 b = sb4[idx];
                float4 a = __ldcg(wA + idx);
                accA += a.x * b.x + a.y * b.y + a.z * b.z + a.w * b.w;
                if (vB) {
                    float4 a2 = __ldcg(wB + idx);
                    accB += a2.x * b.x + a2.y * b.y + a2.z * b.z + a2.w * b.w;
                }
            }
            accA = warpReduce(accA);
            accB = warpReduce(accB);
            if (lane == 0) {
                float lA = accA + bo[r];
                g_logits[r] = lA;
                esum += expf(lA);
                if (vB) {
                    float lB = accB + bo[rB];
                    g_logits[rB] = lB;
                    esum += expf(lB);
                }
            }
        }
        if (lane == 0) swarp[warp] = esum;
        __syncthreads();
        if (t == 0) {
            float s = 0.f;
            #pragma unroll
            for (int w = 0; w < 8; w++) s += swarp[w];
            atomicAdd(&g_expsum, s);
        }
    }
    grid_barrier();

    // ================= Phase 6: log_softmax write ==========================
    {
        float lse = logf(__ldcg(&g_expsum));
        for (int v = blk * NT + t; v < VDIM; v += NB * NT)
            out[v] = __ldcg(&g_logits[v]) - lse;
    }
}

// ---------------------------------------------------------------------------
extern "C" void kernel_launch(void* const* d_in, const int* in_sizes, int n_in,
                              void* d_out, int out_size) {
    const int*   x      = (const int*)  d_in[0];
    const float* hidden = (const float*)d_in[1];
    const float* enc    = (const float*)d_in[2];
    const float* emb    = (const float*)d_in[3];
    const float* Ww     = (const float*)d_in[4];
    const float* bw     = (const float*)d_in[5];
    const float* Wc     = (const float*)d_in[6];
    const float* bc     = (const float*)d_in[7];
    const float* Wih    = (const float*)d_in[8];
    const float* Whh    = (const float*)d_in[9];
    const float* bih    = (const float*)d_in[10];
    const float* bhh    = (const float*)d_in[11];
    const float* Wo     = (const float*)d_in[12];
    const float* bo     = (const float*)d_in[13];
    float* out = (float*)d_out;

    fused_decoder<<<NB, NT>>>(x, hidden, enc, emb, Ww, bw, Wc, bc,
                              Wih, Whh, bih, bhh, Wo, bo, out);
}

// round 6
// speedup vs baseline: 1.5714x; 1.5714x over previous
#include <cuda_runtime.h>
#include <math.h>

#define HDIM 1024
#define LDIM 512
#define VDIM 50257
#define NB   592
#define NT   256
#define NWARPS (NB * 8)

// ---------------- device scratch (no allocations allowed) ----------------
__device__ float g_attn[LDIM];
__device__ float g_wctx[HDIM];
__device__ float g_vout[HDIM];
__device__ float g_gh[3 * HDIM];
__device__ float g_hnew[HDIM];
__device__ float g_logits[VDIM];
__device__ float g_expsum;
__device__ unsigned g_bar_cnt = 0;
__device__ volatile unsigned g_bar_gen = 0;

// ---------------- software grid barrier (all NB blocks co-resident) ------
__device__ __forceinline__ void grid_barrier() {
    __syncthreads();
    if (threadIdx.x == 0) {
        unsigned gen = g_bar_gen;
        __threadfence();
        unsigned t = atomicAdd(&g_bar_cnt, 1u);
        if (t == NB - 1) {
            g_bar_cnt = 0;
            __threadfence();
            g_bar_gen = gen + 1;
        } else {
            while (g_bar_gen == gen) __nanosleep(64);
        }
        __threadfence();
    }
    __syncthreads();
}

__device__ __forceinline__ float warpReduce(float v) {
    #pragma unroll
    for (int o = 16; o; o >>= 1) v += __shfl_down_sync(0xffffffffu, v, o);
    return v;
}

__global__ void __launch_bounds__(NT, 4)
fused_decoder(const int* __restrict__ x, const float* __restrict__ hidden,
              const float* __restrict__ enc, const float* __restrict__ emb,
              const float* __restrict__ Ww, const float* __restrict__ bw,
              const float* __restrict__ Wc, const float* __restrict__ bc,
              const float* __restrict__ Wih, const float* __restrict__ Whh,
              const float* __restrict__ bih, const float* __restrict__ bhh,
              const float* __restrict__ Wo, const float* __restrict__ bo,
              float* __restrict__ out) {
    __shared__ float sbuf[2048];
    __shared__ float sred[256];
    __shared__ float swarp[8];
    __shared__ float s_m, s_inv;

    const int blk = blockIdx.x, t = threadIdx.x;
    const int warp = t >> 5, lane = t & 31;
    float4* sb4 = (float4*)sbuf;

    // ================= Phase 1: attn logits + gh = Whh@h + bhh ============
    // jobs spread as j = warp*NB + blk -> every SM gets ~6 active warps.
    {
        const float4* e4 = (const float4*)(emb + (size_t)x[0] * HDIM);
        const float4* h4 = (const float4*)hidden;
        sb4[t] = e4[t];
        sb4[256 + t] = h4[t];
        if (blk == 0 && t == 0) g_expsum = 0.f;
        __syncthreads();
        int j = warp * NB + blk;          // 0..4735
        if (j < LDIM) {
            // attention row j: 2048-dot against [emb, hidden]
            const float4* w4 = (const float4*)Ww + (size_t)j * 512;
            float acc = 0.f;
            #pragma unroll
            for (int k = 0; k < 16; k++) {
                int idx = k * 32 + lane;
                float4 a = w4[idx], b = sb4[idx];
                acc += a.x * b.x + a.y * b.y + a.z * b.z + a.w * b.w;
            }
            acc = warpReduce(acc);
            if (lane == 0) g_attn[j] = acc + bw[j];
        } else if (j < LDIM + 3 * HDIM) {
            // gh row (1024-dot against hidden)
            int r = j - LDIM;
            const float4* w4 = (const float4*)Whh + (size_t)r * 256;
            float acc = 0.f;
            #pragma unroll
            for (int k = 0; k < 8; k++) {
                int idx = k * 32 + lane;
                float4 a = w4[idx], b = sb4[256 + idx];
                acc += a.x * b.x + a.y * b.y + a.z * b.z + a.w * b.w;
            }
            acc = warpReduce(acc);
            if (lane == 0) g_gh[r] = acc + bhh[r];
        }
        if (j >= LDIM + 3 * HDIM && lane < 8) {
            // spare warps zero g_wctx (1024 floats; plenty of spare warps)
            int z = (j - (LDIM + 3 * HDIM)) * 8 + lane;
            if (z < HDIM) g_wctx[z] = 0.f;
        }
    }
    grid_barrier();

    // ================= Phase 2: softmax (redundant) + wctx ===============
    // one participating block per SM: blk % 4 == 0, pid 0..147 (use 128)
    {
        int pid = blk >> 2;
        bool part = ((blk & 3) == 0) && (pid < 128);
        if (part || blk == 1) {
            sbuf[t] = __ldcg(g_attn + t);
            sbuf[t + 256] = __ldcg(g_attn + t + 256);
            __syncthreads();
            sred[t] = fmaxf(sbuf[t], sbuf[t + 256]);
            __syncthreads();
            #pragma unroll
            for (int o = 128; o; o >>= 1) { if (t < o) sred[t] = fmaxf(sred[t], sred[t + o]); __syncthreads(); }
            if (t == 0) s_m = sred[0];
            __syncthreads();
            float m = s_m;
            sred[t] = expf(sbuf[t] - m) + expf(sbuf[t + 256] - m);
            __syncthreads();
            #pragma unroll
            for (int o = 128; o; o >>= 1) { if (t < o) sred[t] += sred[t + o]; __syncthreads(); }
            if (t == 0) s_inv = 1.f / sred[0];
            __syncthreads();
            float inv = s_inv;

            if (part) {
                int c = pid & 3, lch = pid >> 2;   // 4 col-chunks x 32 L-chunks
                int l0 = lch * 16;
                int col = c * 256 + t;
                float acc = 0.f;
                #pragma unroll
                for (int jj = 0; jj < 16; jj++) {
                    float w = expf(sbuf[l0 + jj] - m);
                    acc += w * enc[(size_t)(l0 + jj) * HDIM + col];
                }
                atomicAdd(&g_wctx[col], acc * inv);
            }
            if (blk == 1) {   // weights output
                out[VDIM + HDIM + t] = expf(sbuf[t] - m) * inv;
                out[VDIM + HDIM + t + 256] = expf(sbuf[t + 256] - m) * inv;
            }
        }
    }
    grid_barrier();

    // ================= Phase 3: vout = relu(Wc @ [emb, wctx] + bc) ========
    // row = warp*NB + blk -> 1-2 active warps on every SM
    {
        const float4* e4 = (const float4*)(emb + (size_t)x[0] * HDIM);
        sb4[t] = e4[t];
        sb4[256 + t] = __ldcg((const float4*)g_wctx + t);
        __syncthreads();
        int row = warp * NB + blk;
        if (row < HDIM) {
            const float4* w4 = (const float4*)Wc + (size_t)row * 512;
            float acc = 0.f;
            #pragma unroll
            for (int k = 0; k < 16; k++) {
                int idx = k * 32 + lane;
                float4 a = w4[idx], b = sb4[idx];
                acc += a.x * b.x + a.y * b.y + a.z * b.z + a.w * b.w;
            }
            acc = warpReduce(acc);
            if (lane == 0) g_vout[row] = fmaxf(acc + bc[row], 0.f);
        }
    }
    grid_barrier();

    // ================= Phase 4: GRU gates + h_new =========================
    {
        sb4[t] = __ldcg((const float4*)g_vout + t);
        __syncthreads();
        int i = warp * NB + blk;
        if (i < HDIM) {
            const float4* wr = (const float4*)Wih + (size_t)i * 256;
            const float4* wz = (const float4*)Wih + (size_t)(i + HDIM) * 256;
            const float4* wn = (const float4*)Wih + (size_t)(i + 2 * HDIM) * 256;
            float a0 = 0.f, a1 = 0.f, a2 = 0.f;
            #pragma unroll
            for (int k = 0; k < 8; k++) {
                int idx = k * 32 + lane;
                float4 b = sb4[idx];
                float4 m0 = wr[idx]; a0 += m0.x * b.x + m0.y * b.y + m0.z * b.z + m0.w * b.w;
                float4 m1 = wz[idx]; a1 += m1.x * b.x + m1.y * b.y + m1.z * b.z + m1.w * b.w;
                float4 m2 = wn[idx]; a2 += m2.x * b.x + m2.y * b.y + m2.z * b.z + m2.w * b.w;
            }
            a0 = warpReduce(a0); a1 = warpReduce(a1); a2 = warpReduce(a2);
            if (lane == 0) {
                float gh_r = __ldcg(&g_gh[i]);
                float gh_z = __ldcg(&g_gh[i + HDIM]);
                float gh_n = __ldcg(&g_gh[i + 2 * HDIM]);
                float gi_r = a0 + bih[i];
                float gi_z = a1 + bih[i + HDIM];
                float gi_n = a2 + bih[i + 2 * HDIM];
                float r = 1.f / (1.f + expf(-(gi_r + gh_r)));
                float z = 1.f / (1.f + expf(-(gi_z + gh_z)));
                float n = tanhf(gi_n + r * gh_n);
                float hn = (1.f - z) * n + z * hidden[i];
                g_hnew[i] = hn;
                out[VDIM + i] = hn;
            }
        }
    }
    grid_barrier();

    // ================= Phase 5: vocab GEMV + exp-sum =======================
    // balanced contiguous rows per warp (10-11 each), 2 rows in flight
    {
        sb4[t] = __ldcg((const float4*)g_hnew + t);
        __syncthreads();
        int g = blk * 8 + warp;
        int start = (int)(((long)g * VDIM) / NWARPS);
        int end   = (int)(((long)(g + 1) * VDIM) / NWARPS);
        float esum = 0.f;
        for (int r = start; r < end; r += 2) {
            int rB = r + 1;
            bool vB = rB < end;
            const float4* wA = (const float4*)Wo + (size_t)r * 256;
            const float4* wB = (const float4*)Wo + (size_t)rB * 256;
            float accA = 0.f, accB = 0.f;
            #pragma unroll
            for (int k = 0; k < 8; k++) {
                int idx = k * 32 + lane;
                float4 b = sb4[idx];
                float4 a = wA[idx];
                accA += a.x * b.x + a.y * b.y + a.z * b.z + a.w * b.w;
                if (vB) {
                    float4 a2 = wB[idx];
                    accB += a2.x * b.x + a2.y * b.y + a2.z * b.z + a2.w * b.w;
                }
            }
            accA = warpReduce(accA);
            accB = warpReduce(accB);
            if (lane == 0) {
                float lA = accA + bo[r];
                g_logits[r] = lA;
                esum += expf(lA);
                if (vB) {
                    float lB = accB + bo[rB];
                    g_logits[rB] = lB;
                    esum += expf(lB);
                }
            }
        }
        if (lane == 0) swarp[warp] = esum;
        __syncthreads();
        if (t == 0) {
            float s = 0.f;
            #pragma unroll
            for (int w = 0; w < 8; w++) s += swarp[w];
            atomicAdd(&g_expsum, s);
        }
    }
    grid_barrier();

    // ================= Phase 6: log_softmax write ==========================
    {
        float lse = logf(__ldcg(&g_expsum));
        for (int v = blk * NT + t; v < VDIM; v += NB * NT)
            out[v] = __ldcg(&g_logits[v]) - lse;
    }
}

// ---------------------------------------------------------------------------
extern "C" void kernel_launch(void* const* d_in, const int* in_sizes, int n_in,
                              void* d_out, int out_size) {
    const int*   x      = (const int*)  d_in[0];
    const float* hidden = (const float*)d_in[1];
    const float* enc    = (const float*)d_in[2];
    const float* emb    = (const float*)d_in[3];
    const float* Ww     = (const float*)d_in[4];
    const float* bw     = (const float*)d_in[5];
    const float* Wc     = (const float*)d_in[6];
    const float* bc     = (const float*)d_in[7];
    const float* Wih    = (const float*)d_in[8];
    const float* Whh    = (const float*)d_in[9];
    const float* bih    = (const float*)d_in[10];
    const float* bhh    = (const float*)d_in[11];
    const float* Wo     = (const float*)d_in[12];
    const float* bo     = (const float*)d_in[13];
    float* out = (float*)d_out;

    fused_decoder<<<NB, NT>>>(x, hidden, enc, emb, Ww, bw, Wc, bc,
                              Wih, Whh, bih, bhh, Wo, bo, out);
}

// round 7
// speedup vs baseline: 1.8821x; 1.1977x over previous
#include <cuda_runtime.h>
#include <math.h>

#define HDIM 1024
#define LDIM 512
#define VDIM 50257
#define NB   592
#define NT   256
#define NWARPS (NB * 8)

// ---------------- device scratch (no allocations allowed) ----------------
__device__ float g_attn[LDIM];
__device__ float g_wctx[HDIM];
__device__ float g_vout[HDIM];
__device__ float g_gh[3 * HDIM];
__device__ float g_hnew[HDIM];
__device__ float g_logits[VDIM];
__device__ float g_expsum;
__device__ unsigned g_bar_cnt = 0;
__device__ volatile unsigned g_bar_gen = 0;

// ---------------- software grid barrier (all NB blocks co-resident) ------
__device__ __forceinline__ void grid_barrier() {
    __syncthreads();
    if (threadIdx.x == 0) {
        unsigned gen = g_bar_gen;
        __threadfence();
        unsigned t = atomicAdd(&g_bar_cnt, 1u);
        if (t == NB - 1) {
            g_bar_cnt = 0;
            __threadfence();
            g_bar_gen = gen + 1;
        } else {
            while (g_bar_gen == gen) __nanosleep(64);
        }
        __threadfence();
    }
    __syncthreads();
}

__device__ __forceinline__ float warpReduce(float v) {
    #pragma unroll
    for (int o = 16; o; o >>= 1) v += __shfl_down_sync(0xffffffffu, v, o);
    return v;
}

__global__ void __launch_bounds__(NT, 4)
fused_decoder(const int* __restrict__ x, const float* __restrict__ hidden,
              const float* __restrict__ enc, const float* __restrict__ emb,
              const float* __restrict__ Ww, const float* __restrict__ bw,
              const float* __restrict__ Wc, const float* __restrict__ bc,
              const float* __restrict__ Wih, const float* __restrict__ Whh,
              const float* __restrict__ bih, const float* __restrict__ bhh,
              const float* __restrict__ Wo, const float* __restrict__ bo,
              float* __restrict__ out) {
    __shared__ float sbuf[2048];
    __shared__ float sred[256];
    __shared__ float swarp[8];
    __shared__ float s_m, s_inv;
    __shared__ float tile[8][12 * 33];   // per-warp row-partials (stride-33 pad)

    const int blk = blockIdx.x, t = threadIdx.x;
    const int warp = t >> 5, lane = t & 31;
    float4* sb4 = (float4*)sbuf;

    // ================= Phase 1: attn logits + gh = Whh@h + bhh ============
    if (blk < 64) {
        const float4* e4 = (const float4*)(emb + (size_t)x[0] * HDIM);
        const float4* h4 = (const float4*)hidden;
        sb4[t] = e4[t];
        sb4[256 + t] = h4[t];
        __syncthreads();
        int row = blk * 8 + warp;
        const float4* w4 = (const float4*)Ww + (size_t)row * 512;
        float acc = 0.f;
        #pragma unroll
        for (int k = 0; k < 16; k++) {
            int idx = k * 32 + lane;
            float4 a = w4[idx], b = sb4[idx];
            acc += a.x * b.x + a.y * b.y + a.z * b.z + a.w * b.w;
        }
        acc = warpReduce(acc);
        if (lane == 0) g_attn[row] = acc + bw[row];
    } else {
        if (blk == 64) {
            g_wctx[t] = 0.f; g_wctx[t + 256] = 0.f;
            g_wctx[t + 512] = 0.f; g_wctx[t + 768] = 0.f;
            if (t == 0) g_expsum = 0.f;
        }
        const float4* h4 = (const float4*)hidden;
        sb4[t] = h4[t];
        __syncthreads();
        int gw = (blk - 64) * 8 + warp;
        for (int r = gw; r < 3 * HDIM; r += (NB - 64) * 8) {
            const float4* w4 = (const float4*)Whh + (size_t)r * 256;
            float acc = 0.f;
            #pragma unroll
            for (int k = 0; k < 8; k++) {
                int idx = k * 32 + lane;
                float4 a = w4[idx], b = sb4[idx];
                acc += a.x * b.x + a.y * b.y + a.z * b.z + a.w * b.w;
            }
            acc = warpReduce(acc);
            if (lane == 0) g_gh[r] = acc + bhh[r];
        }
    }
    grid_barrier();

    // ================= Phase 2: softmax (redundant per block) + wctx ======
    if (blk < 128) {
        sbuf[t] = __ldcg(g_attn + t);
        sbuf[t + 256] = __ldcg(g_attn + t + 256);
        __syncthreads();
        sred[t] = fmaxf(sbuf[t], sbuf[t + 256]);
        __syncthreads();
        #pragma unroll
        for (int o = 128; o; o >>= 1) { if (t < o) sred[t] = fmaxf(sred[t], sred[t + o]); __syncthreads(); }
        if (t == 0) s_m = sred[0];
        __syncthreads();
        float m = s_m;
        sred[t] = expf(sbuf[t] - m) + expf(sbuf[t + 256] - m);
        __syncthreads();
        #pragma unroll
        for (int o = 128; o; o >>= 1) { if (t < o) sred[t] += sred[t + o]; __syncthreads(); }
        if (t == 0) s_inv = 1.f / sred[0];
        __syncthreads();
        float inv = s_inv;

        int c = blk & 3, lch = blk >> 2;       // 4 col-chunks x 32 L-chunks
        int l0 = lch * 16;
        int col = c * 256 + t;
        float acc = 0.f;
        #pragma unroll
        for (int j = 0; j < 16; j++) {
            float w = expf(sbuf[l0 + j] - m);
            acc += w * enc[(size_t)(l0 + j) * HDIM + col];
        }
        atomicAdd(&g_wctx[col], acc * inv);

        if (blk == 0) {   // weights output
            out[VDIM + HDIM + t] = expf(sbuf[t] - m) * inv;
            out[VDIM + HDIM + t + 256] = expf(sbuf[t + 256] - m) * inv;
        }
    }
    grid_barrier();

    // ================= Phase 3: vout = relu(Wc @ [emb, wctx] + bc) ========
    {
        const float4* e4 = (const float4*)(emb + (size_t)x[0] * HDIM);
        sb4[t] = e4[t];
        sb4[256 + t] = __ldcg((const float4*)g_wctx + t);
        __syncthreads();
        if (blk < 128) {
            int row = blk * 8 + warp;
            const float4* w4 = (const float4*)Wc + (size_t)row * 512;
            float acc = 0.f;
            #pragma unroll
            for (int k = 0; k < 16; k++) {
                int idx = k * 32 + lane;
                float4 a = w4[idx], b = sb4[idx];
                acc += a.x * b.x + a.y * b.y + a.z * b.z + a.w * b.w;
            }
            acc = warpReduce(acc);
            if (lane == 0) g_vout[row] = fmaxf(acc + bc[row], 0.f);
        }
    }
    grid_barrier();

    // ================= Phase 4: GRU gates + h_new (warp per output) =======
    {
        sb4[t] = __ldcg((const float4*)g_vout + t);
        __syncthreads();
        if (blk < 128) {
            int i = blk * 8 + warp;   // 0..1023
            const float4* wr = (const float4*)Wih + (size_t)i * 256;
            const float4* wz = (const float4*)Wih + (size_t)(i + HDIM) * 256;
            const float4* wn = (const float4*)Wih + (size_t)(i + 2 * HDIM) * 256;
            float a0 = 0.f, a1 = 0.f, a2 = 0.f;
            #pragma unroll
            for (int k = 0; k < 8; k++) {
                int idx = k * 32 + lane;
                float4 b = sb4[idx];
                float4 m0 = wr[idx]; a0 += m0.x * b.x + m0.y * b.y + m0.z * b.z + m0.w * b.w;
                float4 m1 = wz[idx]; a1 += m1.x * b.x + m1.y * b.y + m1.z * b.z + m1.w * b.w;
                float4 m2 = wn[idx]; a2 += m2.x * b.x + m2.y * b.y + m2.z * b.z + m2.w * b.w;
            }
            a0 = warpReduce(a0); a1 = warpReduce(a1); a2 = warpReduce(a2);
            if (lane == 0) {
                float gh_r = __ldcg(&g_gh[i]);
                float gh_z = __ldcg(&g_gh[i + HDIM]);
                float gh_n = __ldcg(&g_gh[i + 2 * HDIM]);
                float gi_r = a0 + bih[i];
                float gi_z = a1 + bih[i + HDIM];
                float gi_n = a2 + bih[i + 2 * HDIM];
                float r = 1.f / (1.f + expf(-(gi_r + gh_r)));
                float z = 1.f / (1.f + expf(-(gi_z + gh_z)));
                float n = tanhf(gi_n + r * gh_n);
                float hn = (1.f - z) * n + z * hidden[i];
                g_hnew[i] = hn;
                out[VDIM + i] = hn;
            }
        }
    }
    grid_barrier();

    // ====== Phase 5: vocab GEMV, transpose-reduce (no per-row shfl tail) ===
    {
        sb4[t] = __ldcg((const float4*)g_hnew + t);
        __syncthreads();
        int g = blk * 8 + warp;
        int start = (int)(((long)g * VDIM) / NWARPS);
        int end   = (int)(((long)(g + 1) * VDIM) / NWARPS);
        int nrows = end - start;                 // 10 or 11
        float* myTile = tile[warp];

        // independent row iterations: 8 LDG.128 + 32 FFMA + 1 STS each
        for (int i = 0; i < nrows; i++) {
            const float4* w4 = (const float4*)Wo + (size_t)(start + i) * 256;
            float acc = 0.f;
            #pragma unroll
            for (int k = 0; k < 8; k++) {
                int idx = k * 32 + lane;
                float4 a = __ldcs(w4 + idx);
                float4 b = sb4[idx];
                acc += a.x * b.x + a.y * b.y + a.z * b.z + a.w * b.w;
            }
            myTile[i * 33 + lane] = acc;
        }
        __syncwarp();

        // transpose reduce: lane j sums the 32 partials of row j
        float esum = 0.f;
        if (lane < nrows) {
            float s = 0.f;
            #pragma unroll
            for (int l = 0; l < 32; l++) s += myTile[lane * 33 + l];
            float lg = s + bo[start + lane];
            g_logits[start + lane] = lg;
            esum = expf(lg);
        }
        esum = warpReduce(esum);
        if (lane == 0) swarp[warp] = esum;
        __syncthreads();
        if (t == 0) {
            float s = 0.f;
            #pragma unroll
            for (int w = 0; w < 8; w++) s += swarp[w];
            atomicAdd(&g_expsum, s);
        }
    }
    grid_barrier();

    // ================= Phase 6: log_softmax write ==========================
    {
        float lse = logf(__ldcg(&g_expsum));
        for (int v = blk * NT + t; v < VDIM; v += NB * NT)
            out[v] = __ldcg(&g_logits[v]) - lse;
    }
}

// ---------------------------------------------------------------------------
extern "C" void kernel_launch(void* const* d_in, const int* in_sizes, int n_in,
                              void* d_out, int out_size) {
    const int*   x      = (const int*)  d_in[0];
    const float* hidden = (const float*)d_in[1];
    const float* enc    = (const float*)d_in[2];
    const float* emb    = (const float*)d_in[3];
    const float* Ww     = (const float*)d_in[4];
    const float* bw     = (const float*)d_in[5];
    const float* Wc     = (const float*)d_in[6];
    const float* bc     = (const float*)d_in[7];
    const float* Wih    = (const float*)d_in[8];
    const float* Whh    = (const float*)d_in[9];
    const float* bih    = (const float*)d_in[10];
    const float* bhh    = (const float*)d_in[11];
    const float* Wo     = (const float*)d_in[12];
    const float* bo     = (const float*)d_in[13];
    float* out = (float*)d_out;

    fused_decoder<<<NB, NT>>>(x, hidden, enc, emb, Ww, bw, Wc, bc,
                              Wih, Whh, bih, bhh, Wo, bo, out);
}